// round 2
// baseline (speedup 1.0000x reference)
#include <cuda_runtime.h>
#include <math.h>

// Problem constants
constexpr int Bc      = 4;
constexpr int Sc      = 2048;
constexpr int Dc      = 1024;
constexpr int Hc      = 16;
constexpr int DEPTHc  = 64;
constexpr int M_TOT   = Bc * Sc;              // 8192
constexpr long long OUT_ELEMS  = (long long)M_TOT * Dc;          // 8,388,608
constexpr long long ATTN_ELEMS = (long long)Bc * Hc * Sc * Sc;   // 268,435,456
constexpr float SCALE = 0.125f;               // 1/sqrt(64)

// Scratch (device globals: allocation-free per harness rules)
__device__ float g_q[(size_t)M_TOT * Dc];
__device__ float g_k[(size_t)M_TOT * Dc];
__device__ float g_v[(size_t)M_TOT * Dc];
__device__ float g_ctx[(size_t)M_TOT * Dc];
__device__ float g_attn_fb[(size_t)ATTN_ELEMS];   // fallback if harness only wants `out`

// ---------------------------------------------------------------------------
// Projection GEMM: C[M=8192, N=1024] = A[8192,1024] * W[1024,1024] + bias
// BM=BN=64, BK=16, 256 threads, 4x4 per thread.
// split=1: write in split-head layout [B,H,S,DEPTH]; split=0: row-major [M,N].
// ---------------------------------------------------------------------------
__global__ __launch_bounds__(256) void proj_kernel(
    const float* __restrict__ A, const float* __restrict__ W,
    const float* __restrict__ bias, float* __restrict__ out, int split)
{
    __shared__ float As[16][64];   // [k][m]
    __shared__ float Bs[16][64];   // [k][n]

    const int t  = threadIdx.x;
    const int tx = t & 15, ty = t >> 4;
    const int m0 = blockIdx.y * 64;
    const int n0 = blockIdx.x * 64;

    const int a_m = t >> 2;            // 0..63
    const int a_k = (t & 3) * 4;       // 0,4,8,12
    const int b_k = t >> 4;            // 0..15
    const int b_n = (t & 15) * 4;

    float acc[4][4] = {};

    for (int k0 = 0; k0 < Dc; k0 += 16) {
        float4 av = *(const float4*)&A[(size_t)(m0 + a_m) * Dc + k0 + a_k];
        As[a_k + 0][a_m] = av.x; As[a_k + 1][a_m] = av.y;
        As[a_k + 2][a_m] = av.z; As[a_k + 3][a_m] = av.w;
        *(float4*)&Bs[b_k][b_n] =
            *(const float4*)&W[(size_t)(k0 + b_k) * Dc + n0 + b_n];
        __syncthreads();
#pragma unroll
        for (int kk = 0; kk < 16; kk++) {
            float4 a4 = *(const float4*)&As[kk][ty * 4];
            float4 b4 = *(const float4*)&Bs[kk][tx * 4];
            float a[4] = {a4.x, a4.y, a4.z, a4.w};
            float b[4] = {b4.x, b4.y, b4.z, b4.w};
#pragma unroll
            for (int i = 0; i < 4; i++)
#pragma unroll
                for (int j = 0; j < 4; j++)
                    acc[i][j] = fmaf(a[i], b[j], acc[i][j]);
        }
        __syncthreads();
    }

#pragma unroll
    for (int i = 0; i < 4; i++) {
        int m = m0 + ty * 4 + i;
#pragma unroll
        for (int j = 0; j < 4; j++) {
            int n = n0 + tx * 4 + j;
            float v = acc[i][j] + bias[n];
            if (split) {
                int b = m >> 11, s = m & 2047;       // m / 2048, m % 2048
                int h = n >> 6,  d = n & 63;
                out[(((size_t)(b * Hc + h)) * Sc + s) * DEPTHc + d] = v;
            } else {
                out[(size_t)m * Dc + n] = v;
            }
        }
    }
}

// ---------------------------------------------------------------------------
// Scores: attn_raw[bh, m, n] = SCALE * dot(q[bh,m,:], k[bh,n,:])  (K=64)
// 64x64 tile per block, full K in smem.
// ---------------------------------------------------------------------------
__global__ __launch_bounds__(256) void scores_kernel(
    const float* __restrict__ q, const float* __restrict__ k,
    float* __restrict__ attn)
{
    __shared__ float Qs[64][64];   // [d][m]
    __shared__ float Ks[64][64];   // [d][n]

    const int t  = threadIdx.x;
    const int tx = t & 15, ty = t >> 4;
    const int bh = blockIdx.z;
    const int m0 = blockIdx.y * 64;
    const int n0 = blockIdx.x * 64;
    const float* qb = q + (size_t)bh * Sc * DEPTHc;
    const float* kb = k + (size_t)bh * Sc * DEPTHc;

    const int r     = t >> 2;          // 0..63 (row within tile)
    const int dbase = (t & 3) * 16;    // 0,16,32,48
#pragma unroll
    for (int u = 0; u < 4; u++) {
        int d = dbase + u * 4;
        float4 v = *(const float4*)&qb[(size_t)(m0 + r) * DEPTHc + d];
        Qs[d + 0][r] = v.x; Qs[d + 1][r] = v.y;
        Qs[d + 2][r] = v.z; Qs[d + 3][r] = v.w;
        float4 w = *(const float4*)&kb[(size_t)(n0 + r) * DEPTHc + d];
        Ks[d + 0][r] = w.x; Ks[d + 1][r] = w.y;
        Ks[d + 2][r] = w.z; Ks[d + 3][r] = w.w;
    }
    __syncthreads();

    float acc[4][4] = {};
#pragma unroll 16
    for (int d = 0; d < 64; d++) {
        float4 a4 = *(const float4*)&Qs[d][ty * 4];
        float4 b4 = *(const float4*)&Ks[d][tx * 4];
        float a[4] = {a4.x, a4.y, a4.z, a4.w};
        float b[4] = {b4.x, b4.y, b4.z, b4.w};
#pragma unroll
        for (int i = 0; i < 4; i++)
#pragma unroll
            for (int j = 0; j < 4; j++)
                acc[i][j] = fmaf(a[i], b[j], acc[i][j]);
    }

    float* ab = attn + (size_t)bh * Sc * Sc;
#pragma unroll
    for (int i = 0; i < 4; i++) {
        int m = m0 + ty * 4 + i;
        float4 o;
        o.x = acc[i][0] * SCALE; o.y = acc[i][1] * SCALE;
        o.z = acc[i][2] * SCALE; o.w = acc[i][3] * SCALE;
        *(float4*)&ab[(size_t)m * Sc + n0 + tx * 4] = o;
    }
}

// ---------------------------------------------------------------------------
// Softmax in place over each attn row of length 2048. One block (256t) per row.
// Values kept in registers (8 per thread): single global read + write.
// ---------------------------------------------------------------------------
__global__ __launch_bounds__(256) void softmax_kernel(float* __restrict__ attn)
{
    __shared__ float red[32];
    const int t = threadIdx.x;
    float* row = attn + ((size_t)blockIdx.y * Sc + blockIdx.x) * Sc;

    float4 v0 = *(const float4*)&row[t * 4];
    float4 v1 = *(const float4*)&row[t * 4 + 1024];

    float lm = fmaxf(fmaxf(fmaxf(v0.x, v0.y), fmaxf(v0.z, v0.w)),
                     fmaxf(fmaxf(v1.x, v1.y), fmaxf(v1.z, v1.w)));
#pragma unroll
    for (int o = 16; o; o >>= 1)
        lm = fmaxf(lm, __shfl_xor_sync(0xffffffffu, lm, o));
    if ((t & 31) == 0) red[t >> 5] = lm;
    __syncthreads();
    if (t < 32) {
        float r = (t < 8) ? red[t] : -3.4e38f;
#pragma unroll
        for (int o = 4; o; o >>= 1)
            r = fmaxf(r, __shfl_xor_sync(0xffffffffu, r, o));
        if (t == 0) red[0] = r;
    }
    __syncthreads();
    const float mx = red[0];
    __syncthreads();   // everyone has read red[0] before it is reused

    float e[8];
    e[0] = __expf(v0.x - mx); e[1] = __expf(v0.y - mx);
    e[2] = __expf(v0.z - mx); e[3] = __expf(v0.w - mx);
    e[4] = __expf(v1.x - mx); e[5] = __expf(v1.y - mx);
    e[6] = __expf(v1.z - mx); e[7] = __expf(v1.w - mx);

    float ls = 0.f;
#pragma unroll
    for (int i = 0; i < 8; i++) ls += e[i];
#pragma unroll
    for (int o = 16; o; o >>= 1)
        ls += __shfl_xor_sync(0xffffffffu, ls, o);
    if ((t & 31) == 0) red[t >> 5] = ls;
    __syncthreads();
    if (t < 32) {
        float r = (t < 8) ? red[t] : 0.f;
#pragma unroll
        for (int o = 4; o; o >>= 1)
            r += __shfl_xor_sync(0xffffffffu, r, o);
        if (t == 0) red[0] = r;
    }
    __syncthreads();
    const float inv = 1.0f / red[0];

    float4 o0, o1;
    o0.x = e[0] * inv; o0.y = e[1] * inv; o0.z = e[2] * inv; o0.w = e[3] * inv;
    o1.x = e[4] * inv; o1.y = e[5] * inv; o1.z = e[6] * inv; o1.w = e[7] * inv;
    *(float4*)&row[t * 4]        = o0;
    *(float4*)&row[t * 4 + 1024] = o1;
}

// ---------------------------------------------------------------------------
// Context: ctx[bh, m, n] = sum_k attn[bh,m,k] * v[bh,k,n]   (N=64 full per block)
// BM=64, BN=64, BK=32. Output written in merged-head layout [B,S,D].
// ---------------------------------------------------------------------------
__global__ __launch_bounds__(256) void ctx_kernel(
    const float* __restrict__ attn, const float* __restrict__ v,
    float* __restrict__ ctx)
{
    __shared__ float As[32][64];   // [k][m]
    __shared__ float Bs[32][64];   // [k][n]

    const int t  = threadIdx.x;
    const int tx = t & 15, ty = t >> 4;
    const int bh = blockIdx.y;
    const int m0 = blockIdx.x * 64;
    const float* ab = attn + (size_t)bh * Sc * Sc;
    const float* vb = v    + (size_t)bh * Sc * DEPTHc;

    const int a_m = t >> 2;            // 0..63
    const int a_k = (t & 3) * 8;       // 0,8,16,24
    const int b_k = t >> 3;            // 0..31
    const int b_n = (t & 7) * 8;

    float acc[4][4] = {};

    for (int k0 = 0; k0 < Sc; k0 += 32) {
#pragma unroll
        for (int u = 0; u < 2; u++) {
            float4 av = *(const float4*)&ab[(size_t)(m0 + a_m) * Sc + k0 + a_k + u * 4];
            As[a_k + u * 4 + 0][a_m] = av.x; As[a_k + u * 4 + 1][a_m] = av.y;
            As[a_k + u * 4 + 2][a_m] = av.z; As[a_k + u * 4 + 3][a_m] = av.w;
            *(float4*)&Bs[b_k][b_n + u * 4] =
                *(const float4*)&vb[(size_t)(k0 + b_k) * DEPTHc + b_n + u * 4];
        }
        __syncthreads();
#pragma unroll 8
        for (int kk = 0; kk < 32; kk++) {
            float4 a4 = *(const float4*)&As[kk][ty * 4];
            float4 b4 = *(const float4*)&Bs[kk][tx * 4];
            float a[4] = {a4.x, a4.y, a4.z, a4.w};
            float b[4] = {b4.x, b4.y, b4.z, b4.w};
#pragma unroll
            for (int i = 0; i < 4; i++)
#pragma unroll
                for (int j = 0; j < 4; j++)
                    acc[i][j] = fmaf(a[i], b[j], acc[i][j]);
        }
        __syncthreads();
    }

    const int b = bh >> 4, h = bh & 15;
#pragma unroll
    for (int i = 0; i < 4; i++) {
        int m = m0 + ty * 4 + i;
        float4 o;
        o.x = acc[i][0]; o.y = acc[i][1]; o.z = acc[i][2]; o.w = acc[i][3];
        *(float4*)&ctx[((size_t)(b * Sc + m)) * Dc + h * DEPTHc + tx * 4] = o;
    }
}

// ---------------------------------------------------------------------------
extern "C" void kernel_launch(void* const* d_in, const int* in_sizes, int n_in,
                              void* d_out, int out_size)
{
    const float* Q   = (const float*)d_in[0];
    const float* K   = (const float*)d_in[1];
    const float* V   = (const float*)d_in[2];
    const float* WQw = (const float*)d_in[3];
    const float* WQb = (const float*)d_in[4];
    const float* WKw = (const float*)d_in[5];
    const float* WKb = (const float*)d_in[6];
    const float* WVw = (const float*)d_in[7];
    const float* WVb = (const float*)d_in[8];
    const float* WOw = (const float*)d_in[9];
    const float* WOb = (const float*)d_in[10];
    float* out = (float*)d_out;

    float *pq, *pk, *pv, *pctx, *pfb;
    cudaGetSymbolAddress((void**)&pq,   g_q);
    cudaGetSymbolAddress((void**)&pk,   g_k);
    cudaGetSymbolAddress((void**)&pv,   g_v);
    cudaGetSymbolAddress((void**)&pctx, g_ctx);
    cudaGetSymbolAddress((void**)&pfb,  g_attn_fb);

    // attn is the second tuple output; fall back to scratch if harness only
    // allocated space for `out`.
    float* attn = ((long long)out_size >= OUT_ELEMS + ATTN_ELEMS)
                      ? out + OUT_ELEMS : pfb;

    dim3 blk(256);
    dim3 gProj(Dc / 64, M_TOT / 64);           // 16 x 128
    dim3 gScore(Sc / 64, Sc / 64, Bc * Hc);    // 32 x 32 x 64
    dim3 gSoft(Sc, Bc * Hc);                   // 2048 x 64
    dim3 gCtx(Sc / 64, Bc * Hc);               // 32 x 64

    proj_kernel<<<gProj, blk>>>(Q, WQw, WQb, pq, 1);
    proj_kernel<<<gProj, blk>>>(K, WKw, WKb, pk, 1);
    proj_kernel<<<gProj, blk>>>(V, WVw, WVb, pv, 1);
    scores_kernel<<<gScore, blk>>>(pq, pk, attn);
    softmax_kernel<<<gSoft, blk>>>(attn);
    ctx_kernel<<<gCtx, blk>>>(attn, pv, pctx);
    proj_kernel<<<gProj, blk>>>(pctx, WOw, WOb, out, 0);
}

// round 3
// speedup vs baseline: 1.0986x; 1.0986x over previous
#include <cuda_runtime.h>
#include <cuda_bf16.h>
#include <mma.h>
#include <math.h>

using namespace nvcuda;

// Problem constants
constexpr int Bc      = 4;
constexpr int Sc      = 2048;
constexpr int Dc      = 1024;
constexpr int Hc      = 16;
constexpr int DEPTHc  = 64;
constexpr int M_TOT   = Bc * Sc;              // 8192
constexpr long long OUT_ELEMS  = (long long)M_TOT * Dc;          // 8,388,608
constexpr long long ATTN_ELEMS = (long long)Bc * Hc * Sc * Sc;   // 268,435,456
constexpr float SCALE = 0.125f;               // 1/sqrt(64)

// Scratch
__device__ float g_q[(size_t)M_TOT * Dc];
__device__ float g_k[(size_t)M_TOT * Dc];
__device__ float g_v[(size_t)M_TOT * Dc];
__device__ float g_ctx[(size_t)M_TOT * Dc];
__device__ float g_attn_fb[(size_t)ATTN_ELEMS];

__device__ __forceinline__ void split2(float x, __nv_bfloat16& hi, __nv_bfloat16& lo) {
    hi = __float2bfloat16(x);
    lo = __float2bfloat16(x - __bfloat162float(hi));
}

typedef wmma::fragment<wmma::matrix_a, 16, 16, 16, __nv_bfloat16, wmma::row_major> FragA;
typedef wmma::fragment<wmma::matrix_b, 16, 16, 16, __nv_bfloat16, wmma::row_major> FragBR;
typedef wmma::fragment<wmma::matrix_b, 16, 16, 16, __nv_bfloat16, wmma::col_major> FragBC;
typedef wmma::fragment<wmma::accumulator, 16, 16, 16, float> FragC;

// ---------------------------------------------------------------------------
// Projection GEMM (bf16 split, wmma): C[8192,1024] = A @ W + bias
// BM=128, BN=128, BK=32, 8 warps (2m x 4n), warp tile 64x32.
// split=1 -> write [B,H,S,64]; split=0 -> row-major [M,1024].
// ---------------------------------------------------------------------------
constexpr int ALD = 40;    // 32 + 8 pad (bf16 elems)
constexpr int BLD = 136;   // 128 + 8 pad

__global__ __launch_bounds__(256) void proj_tc(
    const float* __restrict__ A, const float* __restrict__ W,
    const float* __restrict__ bias, float* __restrict__ out, int split)
{
    __shared__ __nv_bfloat16 Ah[128 * ALD], Al[128 * ALD];
    __shared__ __nv_bfloat16 Bh[32 * BLD],  Bl[32 * BLD];
    __shared__ float biasTile[16 * BLD];

    const int t  = threadIdx.x;
    const int w  = t >> 5;
    const int wm = w >> 2;          // 0..1
    const int wn = w & 3;           // 0..3
    const int m0 = blockIdx.y * 128;
    const int n0 = blockIdx.x * 128;

    for (int i = t; i < 16 * 128; i += 256) {
        int r = i >> 7, c = i & 127;
        biasTile[r * BLD + c] = bias[n0 + c];
    }

    FragC acc[4][2];
#pragma unroll
    for (int i = 0; i < 4; i++)
#pragma unroll
        for (int j = 0; j < 2; j++) wmma::fill_fragment(acc[i][j], 0.0f);

    const int am = t >> 1, akq = (t & 1) * 16;     // A: row 0..127, col base
    const int bk = t >> 3, bcq = (t & 7) * 16;     // B: row 0..31, col base

    for (int k0 = 0; k0 < Dc; k0 += 32) {
        // load + split A tile 128x32
        const float* asrc = &A[(size_t)(m0 + am) * Dc + k0 + akq];
#pragma unroll
        for (int j = 0; j < 4; j++) {
            float4 v = *(const float4*)(asrc + j * 4);
            int o = am * ALD + akq + j * 4;
            split2(v.x, Ah[o + 0], Al[o + 0]); split2(v.y, Ah[o + 1], Al[o + 1]);
            split2(v.z, Ah[o + 2], Al[o + 2]); split2(v.w, Ah[o + 3], Al[o + 3]);
        }
        // load + split B tile 32x128
        const float* bsrc = &W[(size_t)(k0 + bk) * Dc + n0 + bcq];
#pragma unroll
        for (int j = 0; j < 4; j++) {
            float4 v = *(const float4*)(bsrc + j * 4);
            int o = bk * BLD + bcq + j * 4;
            split2(v.x, Bh[o + 0], Bl[o + 0]); split2(v.y, Bh[o + 1], Bl[o + 1]);
            split2(v.z, Bh[o + 2], Bl[o + 2]); split2(v.w, Bh[o + 3], Bl[o + 3]);
        }
        __syncthreads();

#pragma unroll
        for (int ks = 0; ks < 32; ks += 16) {
            FragA ah[4], al[4];
#pragma unroll
            for (int i = 0; i < 4; i++) {
                wmma::load_matrix_sync(ah[i], &Ah[(wm * 64 + i * 16) * ALD + ks], ALD);
                wmma::load_matrix_sync(al[i], &Al[(wm * 64 + i * 16) * ALD + ks], ALD);
            }
#pragma unroll
            for (int j = 0; j < 2; j++) {
                FragBR bh, bl;
                wmma::load_matrix_sync(bh, &Bh[ks * BLD + wn * 32 + j * 16], BLD);
                wmma::load_matrix_sync(bl, &Bl[ks * BLD + wn * 32 + j * 16], BLD);
#pragma unroll
                for (int i = 0; i < 4; i++) {
                    wmma::mma_sync(acc[i][j], ah[i], bh, acc[i][j]);
                    wmma::mma_sync(acc[i][j], ah[i], bl, acc[i][j]);
                    wmma::mma_sync(acc[i][j], al[i], bh, acc[i][j]);
                }
            }
        }
        __syncthreads();
    }

    // epilogue: bias add via replicated-row bias tile, direct global store
#pragma unroll
    for (int i = 0; i < 4; i++) {
#pragma unroll
        for (int j = 0; j < 2; j++) {
            FragC bf;
            wmma::load_matrix_sync(bf, &biasTile[wn * 32 + j * 16], BLD, wmma::mem_row_major);
#pragma unroll
            for (int e = 0; e < bf.num_elements; e++) acc[i][j].x[e] += bf.x[e];

            int m = m0 + wm * 64 + i * 16;
            int n = n0 + wn * 32 + j * 16;
            if (split) {
                int b = m >> 11, s = m & 2047, h = n >> 6, d = n & 63;
                float* dst = out + (((size_t)(b * Hc + h)) * Sc + s) * DEPTHc + d;
                wmma::store_matrix_sync(dst, acc[i][j], DEPTHc, wmma::mem_row_major);
            } else {
                float* dst = out + (size_t)m * Dc + n;
                wmma::store_matrix_sync(dst, acc[i][j], Dc, wmma::mem_row_major);
            }
        }
    }
}

// ---------------------------------------------------------------------------
// Fused attention: per (bh, 128-row strip): scores + softmax + attn write + ctx
// Two passes over K tiles (64 keys each). bf16 split mma throughout.
// ---------------------------------------------------------------------------
constexpr int QLD = 72;    // 64 + 8 pad (bf16)
constexpr int PSLD = 68;   // fp32 scores pad

// dynamic smem layout (bytes)
constexpr int OFF_QH  = 0;
constexpr int OFF_QL  = OFF_QH + 128 * QLD * 2;
constexpr int OFF_KH  = OFF_QL + 128 * QLD * 2;
constexpr int OFF_KL  = OFF_KH + 64 * QLD * 2;
constexpr int OFF_VH  = OFF_KL + 64 * QLD * 2;
constexpr int OFF_VL  = OFF_VH + 64 * QLD * 2;
constexpr int OFF_PH  = OFF_VL + 64 * QLD * 2;
constexpr int OFF_PL  = OFF_PH + 128 * QLD * 2;
constexpr int OFF_PS  = OFF_PL + 128 * QLD * 2;
constexpr int OFF_RM  = OFF_PS + 128 * PSLD * 4;
constexpr int OFF_RI  = OFF_RM + 128 * 4;
constexpr int SMEM_ATTN = OFF_RI + 128 * 4;     // ~146.9 KB

__global__ __launch_bounds__(256) void attn_fused(
    const float* __restrict__ q, const float* __restrict__ k,
    const float* __restrict__ v, float* __restrict__ attn,
    float* __restrict__ ctx)
{
    extern __shared__ char smraw[];
    __nv_bfloat16* Qh = (__nv_bfloat16*)(smraw + OFF_QH);
    __nv_bfloat16* Ql = (__nv_bfloat16*)(smraw + OFF_QL);
    __nv_bfloat16* Kh = (__nv_bfloat16*)(smraw + OFF_KH);
    __nv_bfloat16* Kl = (__nv_bfloat16*)(smraw + OFF_KL);
    __nv_bfloat16* Vh = (__nv_bfloat16*)(smraw + OFF_VH);
    __nv_bfloat16* Vl = (__nv_bfloat16*)(smraw + OFF_VL);
    __nv_bfloat16* Ph = (__nv_bfloat16*)(smraw + OFF_PH);
    __nv_bfloat16* Pl = (__nv_bfloat16*)(smraw + OFF_PL);
    float* Ps     = (float*)(smraw + OFF_PS);
    float* rowm   = (float*)(smraw + OFF_RM);
    float* rowinv = (float*)(smraw + OFF_RI);

    const int t  = threadIdx.x;
    const int w  = t >> 5;
    const int wm = w >> 1;          // 0..3 (32-row strip within 128)
    const int wn = w & 1;           // 0..1 (32-col strip within 64)
    const int m0 = blockIdx.x * 128;
    const int bh = blockIdx.y;
    const int bb = bh >> 4, hh = bh & 15;

    const float* qb = q + (size_t)bh * Sc * DEPTHc;
    const float* kb = k + (size_t)bh * Sc * DEPTHc;
    const float* vb = v + (size_t)bh * Sc * DEPTHc;

    // load Q strip 128x64 (split)
    {
        int r = t >> 1, c0 = (t & 1) * 32;
        const float* src = &qb[(size_t)(m0 + r) * DEPTHc + c0];
#pragma unroll
        for (int j = 0; j < 8; j++) {
            float4 vv = *(const float4*)(src + j * 4);
            int o = r * QLD + c0 + j * 4;
            split2(vv.x, Qh[o + 0], Ql[o + 0]); split2(vv.y, Qh[o + 1], Ql[o + 1]);
            split2(vv.z, Qh[o + 2], Ql[o + 2]); split2(vv.w, Qh[o + 3], Ql[o + 3]);
        }
    }

    const int lr = t >> 2, lc = (t & 3) * 16;   // 64x64 tile load mapping

    float mrun = -3.4e38f, srun = 0.0f;

    // ---------------- pass 1: row max + sum ----------------
    for (int kt = 0; kt < 32; kt++) {
        const float* src = &kb[(size_t)(kt * 64 + lr) * DEPTHc + lc];
#pragma unroll
        for (int j = 0; j < 4; j++) {
            float4 vv = *(const float4*)(src + j * 4);
            int o = lr * QLD + lc + j * 4;
            split2(vv.x, Kh[o + 0], Kl[o + 0]); split2(vv.y, Kh[o + 1], Kl[o + 1]);
            split2(vv.z, Kh[o + 2], Kl[o + 2]); split2(vv.w, Kh[o + 3], Kl[o + 3]);
        }
        __syncthreads();

        FragC s[2][2];
#pragma unroll
        for (int i = 0; i < 2; i++)
#pragma unroll
            for (int j = 0; j < 2; j++) wmma::fill_fragment(s[i][j], 0.0f);
#pragma unroll
        for (int d0 = 0; d0 < 64; d0 += 16) {
            FragA ah[2], al[2];
            FragBC bhf[2], blf[2];
#pragma unroll
            for (int i = 0; i < 2; i++) {
                wmma::load_matrix_sync(ah[i], &Qh[(wm * 32 + i * 16) * QLD + d0], QLD);
                wmma::load_matrix_sync(al[i], &Ql[(wm * 32 + i * 16) * QLD + d0], QLD);
                wmma::load_matrix_sync(bhf[i], &Kh[(wn * 32 + i * 16) * QLD + d0], QLD);
                wmma::load_matrix_sync(blf[i], &Kl[(wn * 32 + i * 16) * QLD + d0], QLD);
            }
#pragma unroll
            for (int i = 0; i < 2; i++)
#pragma unroll
                for (int j = 0; j < 2; j++) {
                    wmma::mma_sync(s[i][j], ah[i], bhf[j], s[i][j]);
                    wmma::mma_sync(s[i][j], ah[i], blf[j], s[i][j]);
                    wmma::mma_sync(s[i][j], al[i], bhf[j], s[i][j]);
                }
        }
#pragma unroll
        for (int i = 0; i < 2; i++)
#pragma unroll
            for (int j = 0; j < 2; j++)
                wmma::store_matrix_sync(&Ps[(wm * 32 + i * 16) * PSLD + wn * 32 + j * 16],
                                        s[i][j], PSLD, wmma::mem_row_major);
        __syncthreads();

        {   // online max/sum update: thread owns half a row (32 cols)
            int r = t >> 1, c0 = (t & 1) * 32;
            const float* pr = &Ps[r * PSLD + c0];
            float tm = -3.4e38f;
#pragma unroll 8
            for (int i = 0; i < 32; i++) tm = fmaxf(tm, pr[i] * SCALE);
            float mnew = fmaxf(mrun, tm);
            float add = 0.0f;
#pragma unroll 8
            for (int i = 0; i < 32; i++) add += __expf(pr[i] * SCALE - mnew);
            srun = srun * __expf(mrun - mnew) + add;
            mrun = mnew;
        }
        __syncthreads();
    }

    // merge the two half-rows (lanes t, t^1)
    {
        float mo = __shfl_xor_sync(0xffffffffu, mrun, 1);
        float so = __shfl_xor_sync(0xffffffffu, srun, 1);
        float mm = fmaxf(mrun, mo);
        float ss = srun * __expf(mrun - mm) + so * __expf(mo - mm);
        if ((t & 1) == 0) {
            rowm[t >> 1]   = mm;
            rowinv[t >> 1] = 1.0f / ss;
        }
    }
    __syncthreads();

    // ---------------- pass 2: recompute, write attn, accumulate ctx --------
    FragC accC[2][2];
#pragma unroll
    for (int i = 0; i < 2; i++)
#pragma unroll
        for (int j = 0; j < 2; j++) wmma::fill_fragment(accC[i][j], 0.0f);

    for (int kt = 0; kt < 32; kt++) {
        {
            const float* ksrc = &kb[(size_t)(kt * 64 + lr) * DEPTHc + lc];
            const float* vsrc = &vb[(size_t)(kt * 64 + lr) * DEPTHc + lc];
#pragma unroll
            for (int j = 0; j < 4; j++) {
                float4 vv = *(const float4*)(ksrc + j * 4);
                int o = lr * QLD + lc + j * 4;
                split2(vv.x, Kh[o + 0], Kl[o + 0]); split2(vv.y, Kh[o + 1], Kl[o + 1]);
                split2(vv.z, Kh[o + 2], Kl[o + 2]); split2(vv.w, Kh[o + 3], Kl[o + 3]);
                float4 uu = *(const float4*)(vsrc + j * 4);
                split2(uu.x, Vh[o + 0], Vl[o + 0]); split2(uu.y, Vh[o + 1], Vl[o + 1]);
                split2(uu.z, Vh[o + 2], Vl[o + 2]); split2(uu.w, Vh[o + 3], Vl[o + 3]);
            }
        }
        __syncthreads();

        FragC s[2][2];
#pragma unroll
        for (int i = 0; i < 2; i++)
#pragma unroll
            for (int j = 0; j < 2; j++) wmma::fill_fragment(s[i][j], 0.0f);
#pragma unroll
        for (int d0 = 0; d0 < 64; d0 += 16) {
            FragA ah[2], al[2];
            FragBC bhf[2], blf[2];
#pragma unroll
            for (int i = 0; i < 2; i++) {
                wmma::load_matrix_sync(ah[i], &Qh[(wm * 32 + i * 16) * QLD + d0], QLD);
                wmma::load_matrix_sync(al[i], &Ql[(wm * 32 + i * 16) * QLD + d0], QLD);
                wmma::load_matrix_sync(bhf[i], &Kh[(wn * 32 + i * 16) * QLD + d0], QLD);
                wmma::load_matrix_sync(blf[i], &Kl[(wn * 32 + i * 16) * QLD + d0], QLD);
            }
#pragma unroll
            for (int i = 0; i < 2; i++)
#pragma unroll
                for (int j = 0; j < 2; j++) {
                    wmma::mma_sync(s[i][j], ah[i], bhf[j], s[i][j]);
                    wmma::mma_sync(s[i][j], ah[i], blf[j], s[i][j]);
                    wmma::mma_sync(s[i][j], al[i], bhf[j], s[i][j]);
                }
        }
#pragma unroll
        for (int i = 0; i < 2; i++)
#pragma unroll
            for (int j = 0; j < 2; j++)
                wmma::store_matrix_sync(&Ps[(wm * 32 + i * 16) * PSLD + wn * 32 + j * 16],
                                        s[i][j], PSLD, wmma::mem_row_major);
        __syncthreads();

        {   // p = exp(s*SCALE - m) * inv ; write attn + split into Ph/Pl
            int r = t >> 1, c0 = (t & 1) * 32;
            float mr = rowm[r], iv = rowinv[r];
            const float* pr = &Ps[r * PSLD + c0];
            float pv[32];
#pragma unroll 8
            for (int i = 0; i < 32; i++) {
                float p = __expf(pr[i] * SCALE - mr) * iv;
                pv[i] = p;
                int o = r * QLD + c0 + i;
                split2(p, Ph[o], Pl[o]);
            }
            float* adst = attn + ((size_t)bh * Sc + m0 + r) * Sc + kt * 64 + c0;
#pragma unroll
            for (int j = 0; j < 8; j++) {
                float4 ov = make_float4(pv[j * 4], pv[j * 4 + 1], pv[j * 4 + 2], pv[j * 4 + 3]);
                *(float4*)(adst + j * 4) = ov;
            }
        }
        __syncthreads();

        // ctx += P @ V
#pragma unroll
        for (int ks = 0; ks < 64; ks += 16) {
            FragA ph[2], pl[2];
            FragBR vh, vl;
#pragma unroll
            for (int i = 0; i < 2; i++) {
                wmma::load_matrix_sync(ph[i], &Ph[(wm * 32 + i * 16) * QLD + ks], QLD);
                wmma::load_matrix_sync(pl[i], &Pl[(wm * 32 + i * 16) * QLD + ks], QLD);
            }
#pragma unroll
            for (int j = 0; j < 2; j++) {
                wmma::load_matrix_sync(vh, &Vh[ks * QLD + wn * 32 + j * 16], QLD);
                wmma::load_matrix_sync(vl, &Vl[ks * QLD + wn * 32 + j * 16], QLD);
#pragma unroll
                for (int i = 0; i < 2; i++) {
                    wmma::mma_sync(accC[i][j], ph[i], vh, accC[i][j]);
                    wmma::mma_sync(accC[i][j], ph[i], vl, accC[i][j]);
                    wmma::mma_sync(accC[i][j], pl[i], vh, accC[i][j]);
                }
            }
        }
        __syncthreads();   // protect Kh/Vh/Ph before next iteration's loads
    }

    // store ctx in merged-head layout [B,S,D]
#pragma unroll
    for (int i = 0; i < 2; i++)
#pragma unroll
        for (int j = 0; j < 2; j++) {
            int m = m0 + wm * 32 + i * 16;
            int d = hh * DEPTHc + wn * 32 + j * 16;
            float* dst = ctx + ((size_t)(bb * Sc + m)) * Dc + d;
            wmma::store_matrix_sync(dst, accC[i][j], Dc, wmma::mem_row_major);
        }
}

// ---------------------------------------------------------------------------
extern "C" void kernel_launch(void* const* d_in, const int* in_sizes, int n_in,
                              void* d_out, int out_size)
{
    const float* Q   = (const float*)d_in[0];
    const float* K   = (const float*)d_in[1];
    const float* V   = (const float*)d_in[2];
    const float* WQw = (const float*)d_in[3];
    const float* WQb = (const float*)d_in[4];
    const float* WKw = (const float*)d_in[5];
    const float* WKb = (const float*)d_in[6];
    const float* WVw = (const float*)d_in[7];
    const float* WVb = (const float*)d_in[8];
    const float* WOw = (const float*)d_in[9];
    const float* WOb = (const float*)d_in[10];
    float* out = (float*)d_out;

    float *pq, *pk, *pv, *pctx, *pfb;
    cudaGetSymbolAddress((void**)&pq,   g_q);
    cudaGetSymbolAddress((void**)&pk,   g_k);
    cudaGetSymbolAddress((void**)&pv,   g_v);
    cudaGetSymbolAddress((void**)&pctx, g_ctx);
    cudaGetSymbolAddress((void**)&pfb,  g_attn_fb);

    float* attn = ((long long)out_size >= OUT_ELEMS + ATTN_ELEMS)
                      ? out + OUT_ELEMS : pfb;

    static int smem_set = 0;
    if (!smem_set) {
        cudaFuncSetAttribute(attn_fused, cudaFuncAttributeMaxDynamicSharedMemorySize,
                             SMEM_ATTN);
        smem_set = 1;
    }

    dim3 blk(256);
    dim3 gProj(Dc / 128, M_TOT / 128);          // 8 x 64
    dim3 gAttn(Sc / 128, Bc * Hc);              // 16 x 64

    proj_tc<<<gProj, blk>>>(Q, WQw, WQb, pq, 1);
    proj_tc<<<gProj, blk>>>(K, WKw, WKb, pk, 1);
    proj_tc<<<gProj, blk>>>(V, WVw, WVb, pv, 1);
    attn_fused<<<gAttn, blk, SMEM_ATTN>>>(pq, pk, pv, attn, pctx);
    proj_tc<<<gProj, blk>>>(pctx, WOw, WOb, out, 0);
}

// round 6
// speedup vs baseline: 1.3856x; 1.2613x over previous
#include <cuda_runtime.h>
#include <cuda_bf16.h>
#include <mma.h>
#include <math.h>

using namespace nvcuda;

constexpr int Bc      = 4;
constexpr int Sc      = 2048;
constexpr int Dc      = 1024;
constexpr int Hc      = 16;
constexpr int DEPTHc  = 64;
constexpr int M_TOT   = Bc * Sc;              // 8192
constexpr long long OUT_ELEMS  = (long long)M_TOT * Dc;
constexpr long long ATTN_ELEMS = (long long)Bc * Hc * Sc * Sc;   // 268,435,456
constexpr float SCALE = 0.125f;

__device__ float g_q[(size_t)M_TOT * Dc];
__device__ float g_k[(size_t)M_TOT * Dc];
__device__ float g_v[(size_t)M_TOT * Dc];
__device__ float g_ctx[(size_t)M_TOT * Dc];
__device__ float g_inv[(size_t)Bc * Hc * Sc];
__device__ float g_attn_fb[(size_t)ATTN_ELEMS];

__device__ __forceinline__ void split2(float x, __nv_bfloat16& hi, __nv_bfloat16& lo) {
    hi = __float2bfloat16(x);
    lo = __float2bfloat16(x - __bfloat162float(hi));
}

typedef wmma::fragment<wmma::matrix_a, 16, 16, 16, __nv_bfloat16, wmma::row_major> FragA;
typedef wmma::fragment<wmma::matrix_b, 16, 16, 16, __nv_bfloat16, wmma::row_major> FragBR;
typedef wmma::fragment<wmma::matrix_b, 16, 16, 16, __nv_bfloat16, wmma::col_major> FragBC;
typedef wmma::fragment<wmma::accumulator, 16, 16, 16, float> FragC;

// ---------------------------------------------------------------------------
// Projection GEMM core (bf16 split, wmma): C[8192,1024] = A @ W + bias
// BM=128, BN=128, BK=32, 8 warps (2m x 4n).
// ---------------------------------------------------------------------------
constexpr int ALD = 40;
constexpr int BLD = 136;

__device__ __forceinline__ void proj_body(
    const float* __restrict__ A, const float* __restrict__ W,
    const float* __restrict__ bias, float* __restrict__ out, int split)
{
    __shared__ __nv_bfloat16 Ah[128 * ALD], Al[128 * ALD];
    __shared__ __nv_bfloat16 Bh[32 * BLD],  Bl[32 * BLD];
    __shared__ float biasTile[16 * BLD];

    const int t  = threadIdx.x;
    const int w  = t >> 5;
    const int wm = w >> 2;
    const int wn = w & 3;
    const int m0 = blockIdx.y * 128;
    const int n0 = blockIdx.x * 128;

    for (int i = t; i < 16 * 128; i += 256) {
        int r = i >> 7, c = i & 127;
        biasTile[r * BLD + c] = bias[n0 + c];
    }

    FragC acc[4][2];
#pragma unroll
    for (int i = 0; i < 4; i++)
#pragma unroll
        for (int j = 0; j < 2; j++) wmma::fill_fragment(acc[i][j], 0.0f);

    const int am = t >> 1, akq = (t & 1) * 16;
    const int bk = t >> 3, bcq = (t & 7) * 16;

    for (int k0 = 0; k0 < Dc; k0 += 32) {
        const float* asrc = &A[(size_t)(m0 + am) * Dc + k0 + akq];
#pragma unroll
        for (int j = 0; j < 4; j++) {
            float4 v = *(const float4*)(asrc + j * 4);
            int o = am * ALD + akq + j * 4;
            split2(v.x, Ah[o + 0], Al[o + 0]); split2(v.y, Ah[o + 1], Al[o + 1]);
            split2(v.z, Ah[o + 2], Al[o + 2]); split2(v.w, Ah[o + 3], Al[o + 3]);
        }
        const float* bsrc = &W[(size_t)(k0 + bk) * Dc + n0 + bcq];
#pragma unroll
        for (int j = 0; j < 4; j++) {
            float4 v = *(const float4*)(bsrc + j * 4);
            int o = bk * BLD + bcq + j * 4;
            split2(v.x, Bh[o + 0], Bl[o + 0]); split2(v.y, Bh[o + 1], Bl[o + 1]);
            split2(v.z, Bh[o + 2], Bl[o + 2]); split2(v.w, Bh[o + 3], Bl[o + 3]);
        }
        __syncthreads();

#pragma unroll
        for (int ks = 0; ks < 32; ks += 16) {
            FragA ah[4], al[4];
#pragma unroll
            for (int i = 0; i < 4; i++) {
                wmma::load_matrix_sync(ah[i], &Ah[(wm * 64 + i * 16) * ALD + ks], ALD);
                wmma::load_matrix_sync(al[i], &Al[(wm * 64 + i * 16) * ALD + ks], ALD);
            }
#pragma unroll
            for (int j = 0; j < 2; j++) {
                FragBR bh, bl;
                wmma::load_matrix_sync(bh, &Bh[ks * BLD + wn * 32 + j * 16], BLD);
                wmma::load_matrix_sync(bl, &Bl[ks * BLD + wn * 32 + j * 16], BLD);
#pragma unroll
                for (int i = 0; i < 4; i++) {
                    wmma::mma_sync(acc[i][j], ah[i], bh, acc[i][j]);
                    wmma::mma_sync(acc[i][j], ah[i], bl, acc[i][j]);
                    wmma::mma_sync(acc[i][j], al[i], bh, acc[i][j]);
                }
            }
        }
        __syncthreads();
    }

#pragma unroll
    for (int i = 0; i < 4; i++) {
#pragma unroll
        for (int j = 0; j < 2; j++) {
            FragC bf;
            wmma::load_matrix_sync(bf, &biasTile[wn * 32 + j * 16], BLD, wmma::mem_row_major);
#pragma unroll
            for (int e = 0; e < bf.num_elements; e++) acc[i][j].x[e] += bf.x[e];

            int m = m0 + wm * 64 + i * 16;
            int n = n0 + wn * 32 + j * 16;
            if (split) {
                int b = m >> 11, s = m & 2047, h = n >> 6, d = n & 63;
                float* dst = out + (((size_t)(b * Hc + h)) * Sc + s) * DEPTHc + d;
                wmma::store_matrix_sync(dst, acc[i][j], DEPTHc, wmma::mem_row_major);
            } else {
                float* dst = out + (size_t)m * Dc + n;
                wmma::store_matrix_sync(dst, acc[i][j], Dc, wmma::mem_row_major);
            }
        }
    }
}

// Fused QKV projection: blockIdx.z selects which of the three GEMMs.
__global__ __launch_bounds__(256) void proj_qkv(
    const float* __restrict__ Q, const float* __restrict__ K, const float* __restrict__ V,
    const float* __restrict__ WQ, const float* __restrict__ WK, const float* __restrict__ WV,
    const float* __restrict__ bQ, const float* __restrict__ bK, const float* __restrict__ bV,
    float* __restrict__ oq, float* __restrict__ ok, float* __restrict__ ov)
{
    int z = blockIdx.z;
    const float* A = (z == 0) ? Q : (z == 1) ? K : V;
    const float* W = (z == 0) ? WQ : (z == 1) ? WK : WV;
    const float* b = (z == 0) ? bQ : (z == 1) ? bK : bV;
    float* o       = (z == 0) ? oq : (z == 1) ? ok : ov;
    proj_body(A, W, b, o, 1);
}

__global__ __launch_bounds__(256) void proj_o(
    const float* __restrict__ A, const float* __restrict__ W,
    const float* __restrict__ bias, float* __restrict__ out)
{
    proj_body(A, W, bias, out, 0);
}

// ---------------------------------------------------------------------------
// Fused attention, single pass, no-max softmax:
//   per (bh, 64-row strip): p = exp(scale*s) written unnormalized to attn,
//   rowsum accumulated; ctx = (P@V)/rowsum. attn rescaled by a second kernel.
// ---------------------------------------------------------------------------
constexpr int QLD  = 72;   // 64 + 8 pad (bf16)
constexpr int PSLD = 68;   // fp32 pad

constexpr int SZ_BF = 64 * QLD * 2;       // 9216 B per bf16 array
constexpr int OFF_QH = 0;
constexpr int OFF_QL = OFF_QH + SZ_BF;
constexpr int OFF_KH = OFF_QL + SZ_BF;
constexpr int OFF_KL = OFF_KH + SZ_BF;
constexpr int OFF_VH = OFF_KL + SZ_BF;
constexpr int OFF_VL = OFF_VH + SZ_BF;
constexpr int OFF_PH = OFF_VL + SZ_BF;
constexpr int OFF_PL = OFF_PH + SZ_BF;
constexpr int OFF_PS = OFF_PL + SZ_BF;
constexpr int OFF_RI = OFF_PS + 64 * PSLD * 4;
constexpr int SMEM_ATTN = OFF_RI + 64 * 4;   // ~91.6 KB -> 2 CTAs/SM

__global__ __launch_bounds__(256) void attn_fused(
    const float* __restrict__ q, const float* __restrict__ k,
    const float* __restrict__ v, float* __restrict__ attn,
    float* __restrict__ ctx, float* __restrict__ invout)
{
    extern __shared__ char smraw[];
    __nv_bfloat16* Qh = (__nv_bfloat16*)(smraw + OFF_QH);
    __nv_bfloat16* Ql = (__nv_bfloat16*)(smraw + OFF_QL);
    __nv_bfloat16* Kh = (__nv_bfloat16*)(smraw + OFF_KH);
    __nv_bfloat16* Kl = (__nv_bfloat16*)(smraw + OFF_KL);
    __nv_bfloat16* Vh = (__nv_bfloat16*)(smraw + OFF_VH);
    __nv_bfloat16* Vl = (__nv_bfloat16*)(smraw + OFF_VL);
    __nv_bfloat16* Ph = (__nv_bfloat16*)(smraw + OFF_PH);
    __nv_bfloat16* Pl = (__nv_bfloat16*)(smraw + OFF_PL);
    float* Ps     = (float*)(smraw + OFF_PS);
    float* rowinv = (float*)(smraw + OFF_RI);

    const int t  = threadIdx.x;
    const int w  = t >> 5;
    const int wm = w >> 1;          // 0..3 : 16-row strip
    const int wn = w & 1;           // 0..1 : 32-col strip
    const int m0 = blockIdx.x * 64;
    const int bh = blockIdx.y;
    const int bb = bh >> 4, hh = bh & 15;

    const float* qb = q + (size_t)bh * Sc * DEPTHc;
    const float* kb = k + (size_t)bh * Sc * DEPTHc;
    const float* vb = v + (size_t)bh * Sc * DEPTHc;

    const int lr = t >> 2, lc = (t & 3) * 16;   // 64x64 tile loads

    // load Q strip 64x64 (split)
    {
        const float* src = &qb[(size_t)(m0 + lr) * DEPTHc + lc];
#pragma unroll
        for (int j = 0; j < 4; j++) {
            float4 vv = *(const float4*)(src + j * 4);
            int o = lr * QLD + lc + j * 4;
            split2(vv.x, Qh[o + 0], Ql[o + 0]); split2(vv.y, Qh[o + 1], Ql[o + 1]);
            split2(vv.z, Qh[o + 2], Ql[o + 2]); split2(vv.w, Qh[o + 3], Ql[o + 3]);
        }
    }

    FragC accC[2];
#pragma unroll
    for (int j = 0; j < 2; j++) wmma::fill_fragment(accC[j], 0.0f);
    float rowsum = 0.0f;

    const int cr = t >> 2;            // row owned in convert step (0..63)
    const int cb = (t & 3) * 4;       // col base; cols cb + 16*j

    for (int kt = 0; kt < 32; kt++) {
        // load K, V tiles (split)
        {
            const float* ksrc = &kb[(size_t)(kt * 64 + lr) * DEPTHc + lc];
            const float* vsrc = &vb[(size_t)(kt * 64 + lr) * DEPTHc + lc];
#pragma unroll
            for (int j = 0; j < 4; j++) {
                float4 vv = *(const float4*)(ksrc + j * 4);
                int o = lr * QLD + lc + j * 4;
                split2(vv.x, Kh[o + 0], Kl[o + 0]); split2(vv.y, Kh[o + 1], Kl[o + 1]);
                split2(vv.z, Kh[o + 2], Kl[o + 2]); split2(vv.w, Kh[o + 3], Kl[o + 3]);
                float4 uu = *(const float4*)(vsrc + j * 4);
                split2(uu.x, Vh[o + 0], Vl[o + 0]); split2(uu.y, Vh[o + 1], Vl[o + 1]);
                split2(uu.z, Vh[o + 2], Vl[o + 2]); split2(uu.w, Vh[o + 3], Vl[o + 3]);
            }
        }
        __syncthreads();

        // scores: S = Q @ K^T  (16x64 per warp-row, 32 cols per warp)
        FragC s[2];
#pragma unroll
        for (int j = 0; j < 2; j++) wmma::fill_fragment(s[j], 0.0f);
#pragma unroll
        for (int d0 = 0; d0 < 64; d0 += 16) {
            FragA ah, al;
            wmma::load_matrix_sync(ah, &Qh[(wm * 16) * QLD + d0], QLD);
            wmma::load_matrix_sync(al, &Ql[(wm * 16) * QLD + d0], QLD);
#pragma unroll
            for (int j = 0; j < 2; j++) {
                FragBC bhf, blf;
                wmma::load_matrix_sync(bhf, &Kh[(wn * 32 + j * 16) * QLD + d0], QLD);
                wmma::load_matrix_sync(blf, &Kl[(wn * 32 + j * 16) * QLD + d0], QLD);
                wmma::mma_sync(s[j], ah, bhf, s[j]);
                wmma::mma_sync(s[j], ah, blf, s[j]);
                wmma::mma_sync(s[j], al, bhf, s[j]);
            }
        }
#pragma unroll
        for (int j = 0; j < 2; j++)
            wmma::store_matrix_sync(&Ps[(wm * 16) * PSLD + wn * 32 + j * 16],
                                    s[j], PSLD, wmma::mem_row_major);
        __syncthreads();

        // convert: p = exp(scale*s), write unnormalized attn, split to Ph/Pl
        {
            float* adst = attn + ((size_t)bh * Sc + m0 + cr) * Sc + kt * 64;
            float lsum = 0.0f;
#pragma unroll
            for (int j = 0; j < 4; j++) {
                int c = cb + j * 16;
                float4 sv = *(const float4*)&Ps[cr * PSLD + c];
                float4 pv;
                pv.x = __expf(fminf(sv.x * SCALE, 80.0f));
                pv.y = __expf(fminf(sv.y * SCALE, 80.0f));
                pv.z = __expf(fminf(sv.z * SCALE, 80.0f));
                pv.w = __expf(fminf(sv.w * SCALE, 80.0f));
                lsum += pv.x + pv.y + pv.z + pv.w;
                *(float4*)(adst + c) = pv;
                int o = cr * QLD + c;
                split2(pv.x, Ph[o + 0], Pl[o + 0]); split2(pv.y, Ph[o + 1], Pl[o + 1]);
                split2(pv.z, Ph[o + 2], Pl[o + 2]); split2(pv.w, Ph[o + 3], Pl[o + 3]);
            }
            rowsum += lsum;
        }
        __syncthreads();

        // ctx += P @ V
#pragma unroll
        for (int ks = 0; ks < 64; ks += 16) {
            FragA ph, pl;
            wmma::load_matrix_sync(ph, &Ph[(wm * 16) * QLD + ks], QLD);
            wmma::load_matrix_sync(pl, &Pl[(wm * 16) * QLD + ks], QLD);
#pragma unroll
            for (int j = 0; j < 2; j++) {
                FragBR vh, vl;
                wmma::load_matrix_sync(vh, &Vh[ks * QLD + wn * 32 + j * 16], QLD);
                wmma::load_matrix_sync(vl, &Vl[ks * QLD + wn * 32 + j * 16], QLD);
                wmma::mma_sync(accC[j], ph, vh, accC[j]);
                wmma::mma_sync(accC[j], ph, vl, accC[j]);
                wmma::mma_sync(accC[j], pl, vh, accC[j]);
            }
        }
        __syncthreads();
    }

    // rowsum merge across the 4 threads owning each row
    {
        float rs = rowsum;
        rs += __shfl_xor_sync(0xffffffffu, rs, 1);
        rs += __shfl_xor_sync(0xffffffffu, rs, 2);
        float iv = 1.0f / rs;
        if ((t & 3) == 0) {
            rowinv[cr] = iv;
            invout[(size_t)bh * Sc + m0 + cr] = iv;
        }
    }
    __syncthreads();

    // scale ctx rows by 1/rowsum via Ps round-trip, write merged-head layout
#pragma unroll
    for (int j = 0; j < 2; j++)
        wmma::store_matrix_sync(&Ps[(wm * 16) * PSLD + wn * 32 + j * 16],
                                accC[j], PSLD, wmma::mem_row_major);
    __syncthreads();
    {
        float iv = rowinv[cr];
        float* cdst = ctx + ((size_t)(bb * Sc) + m0 + cr) * Dc + hh * DEPTHc;
#pragma unroll
        for (int j = 0; j < 4; j++) {
            int c = cb + j * 16;
            float4 vv = *(const float4*)&Ps[cr * PSLD + c];
            vv.x *= iv; vv.y *= iv; vv.z *= iv; vv.w *= iv;
            *(float4*)(cdst + c) = vv;
        }
    }
}

// ---------------------------------------------------------------------------
// Rescale attn in place: attn[row, :] *= inv[row]
// ---------------------------------------------------------------------------
__global__ __launch_bounds__(256) void rescale_attn(
    float* __restrict__ attn, const float* __restrict__ inv)
{
    size_t i = (size_t)blockIdx.x * blockDim.x + threadIdx.x;   // float4 index
    float iv = __ldg(&inv[i >> 9]);                             // 512 float4 per row
    float4* p = (float4*)attn;
    float4 vv = p[i];
    vv.x *= iv; vv.y *= iv; vv.z *= iv; vv.w *= iv;
    p[i] = vv;
}

// ---------------------------------------------------------------------------
extern "C" void kernel_launch(void* const* d_in, const int* in_sizes, int n_in,
                              void* d_out, int out_size)
{
    const float* Q   = (const float*)d_in[0];
    const float* K   = (const float*)d_in[1];
    const float* V   = (const float*)d_in[2];
    const float* WQw = (const float*)d_in[3];
    const float* WQb = (const float*)d_in[4];
    const float* WKw = (const float*)d_in[5];
    const float* WKb = (const float*)d_in[6];
    const float* WVw = (const float*)d_in[7];
    const float* WVb = (const float*)d_in[8];
    const float* WOw = (const float*)d_in[9];
    const float* WOb = (const float*)d_in[10];
    float* out = (float*)d_out;

    float *pq, *pk, *pv, *pctx, *pfb, *pinv;
    cudaGetSymbolAddress((void**)&pq,   g_q);
    cudaGetSymbolAddress((void**)&pk,   g_k);
    cudaGetSymbolAddress((void**)&pv,   g_v);
    cudaGetSymbolAddress((void**)&pctx, g_ctx);
    cudaGetSymbolAddress((void**)&pfb,  g_attn_fb);
    cudaGetSymbolAddress((void**)&pinv, g_inv);

    float* attn = ((long long)out_size >= OUT_ELEMS + ATTN_ELEMS)
                      ? out + OUT_ELEMS : pfb;

    static int smem_set = 0;
    if (!smem_set) {
        cudaFuncSetAttribute(attn_fused, cudaFuncAttributeMaxDynamicSharedMemorySize,
                             SMEM_ATTN);
        smem_set = 1;
    }

    dim3 blk(256);
    dim3 gProjQKV(Dc / 128, M_TOT / 128, 3);     // 8 x 64 x 3
    dim3 gProjO(Dc / 128, M_TOT / 128);          // 8 x 64
    dim3 gAttn(Sc / 64, Bc * Hc);                // 32 x 64
    dim3 gResc((unsigned)(ATTN_ELEMS / 4 / 256));

    proj_qkv<<<gProjQKV, blk>>>(Q, K, V, WQw, WKw, WVw, WQb, WKb, WVb, pq, pk, pv);
    attn_fused<<<gAttn, blk, SMEM_ATTN>>>(pq, pk, pv, attn, pctx, pinv);
    rescale_attn<<<gResc, blk>>>(attn, pinv);
    proj_o<<<gProjO, blk>>>(pctx, WOw, WOb, out);
}

// round 10
// speedup vs baseline: 1.9168x; 1.3834x over previous
#include <cuda_runtime.h>
#include <cuda_bf16.h>
#include <mma.h>
#include <math.h>

using namespace nvcuda;

constexpr int Bc      = 4;
constexpr int Sc      = 2048;
constexpr int Dc      = 1024;
constexpr int Hc      = 16;
constexpr int DEPTHc  = 64;
constexpr int M_TOT   = Bc * Sc;              // 8192
constexpr long long OUT_ELEMS  = (long long)M_TOT * Dc;
constexpr long long ATTN_ELEMS = (long long)Bc * Hc * Sc * Sc;
constexpr float SCALE = 0.125f;

constexpr size_t ACT_N = (size_t)M_TOT * Dc;     // 8,388,608
constexpr size_t W_N   = (size_t)Dc * Dc;        // 1,048,576

// ---- device scratch (no allocations allowed) ----
__device__ __nv_bfloat16 g_wh[4 * W_N],  g_wl[4 * W_N];     // WQ,WK,WV,WO split
__device__ __nv_bfloat16 g_inh[3 * ACT_N], g_inl[3 * ACT_N]; // Q,K,V inputs split
__device__ __nv_bfloat16 g_qh[ACT_N], g_ql[ACT_N];           // split-head layout
__device__ __nv_bfloat16 g_kh[ACT_N], g_kl[ACT_N];
__device__ __nv_bfloat16 g_vh[ACT_N], g_vl[ACT_N];
__device__ __nv_bfloat16 g_ctxh[ACT_N], g_ctxl[ACT_N];       // merged-head layout
__device__ float g_inv[(size_t)Bc * Hc * Sc];
__device__ float g_attn_fb[(size_t)ATTN_ELEMS];

__device__ __forceinline__ void split2(float x, __nv_bfloat16& hi, __nv_bfloat16& lo) {
    hi = __float2bfloat16(x);
    lo = __float2bfloat16(x - __bfloat162float(hi));
}

typedef wmma::fragment<wmma::matrix_a, 16, 16, 16, __nv_bfloat16, wmma::row_major> FragA;
typedef wmma::fragment<wmma::matrix_b, 16, 16, 16, __nv_bfloat16, wmma::row_major> FragBR;
typedef wmma::fragment<wmma::matrix_b, 16, 16, 16, __nv_bfloat16, wmma::col_major> FragBC;
typedef wmma::fragment<wmma::accumulator, 16, 16, 16, float> FragC;

// ---------------------------------------------------------------------------
// Pre-split kernels: fp32 -> (bf16 hi, bf16 lo)
// ---------------------------------------------------------------------------
__global__ __launch_bounds__(256) void presplit_w(
    const float* __restrict__ w0, const float* __restrict__ w1,
    const float* __restrict__ w2, const float* __restrict__ w3,
    __nv_bfloat16* __restrict__ h, __nv_bfloat16* __restrict__ l)
{
    int z = blockIdx.y;
    const float* src = (z == 0) ? w0 : (z == 1) ? w1 : (z == 2) ? w2 : w3;
    size_t off = (size_t)z * W_N;
    size_t i = ((size_t)blockIdx.x * 256 + threadIdx.x) * 8;
    float4 a = *(const float4*)(src + i);
    float4 b = *(const float4*)(src + i + 4);
    __nv_bfloat16 hh[8], ll[8];
    split2(a.x, hh[0], ll[0]); split2(a.y, hh[1], ll[1]);
    split2(a.z, hh[2], ll[2]); split2(a.w, hh[3], ll[3]);
    split2(b.x, hh[4], ll[4]); split2(b.y, hh[5], ll[5]);
    split2(b.z, hh[6], ll[6]); split2(b.w, hh[7], ll[7]);
    *(uint4*)(h + off + i) = *(uint4*)hh;
    *(uint4*)(l + off + i) = *(uint4*)ll;
}

__global__ __launch_bounds__(256) void presplit_in(
    const float* __restrict__ a0, const float* __restrict__ a1,
    const float* __restrict__ a2,
    __nv_bfloat16* __restrict__ h, __nv_bfloat16* __restrict__ l)
{
    int z = blockIdx.y;
    const float* src = (z == 0) ? a0 : (z == 1) ? a1 : a2;
    size_t off = (size_t)z * ACT_N;
    size_t i = ((size_t)blockIdx.x * 256 + threadIdx.x) * 8;
    float4 a = *(const float4*)(src + i);
    float4 b = *(const float4*)(src + i + 4);
    __nv_bfloat16 hh[8], ll[8];
    split2(a.x, hh[0], ll[0]); split2(a.y, hh[1], ll[1]);
    split2(a.z, hh[2], ll[2]); split2(a.w, hh[3], ll[3]);
    split2(b.x, hh[4], ll[4]); split2(b.y, hh[5], ll[5]);
    split2(b.z, hh[6], ll[6]); split2(b.w, hh[7], ll[7]);
    *(uint4*)(h + off + i) = *(uint4*)hh;
    *(uint4*)(l + off + i) = *(uint4*)ll;
}

// ---------------------------------------------------------------------------
// Projection GEMM (pre-split bf16 in, double-buffered smem):
//   C[8192,1024] = A @ W + bias.  BM=BN=128, BK=32, 8 warps (2m x 4n).
//   split=1 -> write split-head bf16 hi/lo;  split=0 -> float row-major.
// ---------------------------------------------------------------------------
constexpr int ALD2 = 40;    // 32+8 pad
constexpr int BLD2 = 136;   // 128+8 pad
constexpr int SLD  = 132;   // stage pad

constexpr int SZ_A = 128 * ALD2 * 2;   // 10240 B
constexpr int SZ_B = 32 * BLD2 * 2;    // 8704 B
constexpr int P_AH0 = 0,            P_AH1 = SZ_A;
constexpr int P_AL0 = 2 * SZ_A,     P_AL1 = 3 * SZ_A;
constexpr int P_B0  = 4 * SZ_A;
constexpr int P_BH0 = P_B0,             P_BH1 = P_B0 + SZ_B;
constexpr int P_BL0 = P_B0 + 2 * SZ_B,  P_BL1 = P_B0 + 3 * SZ_B;
constexpr int SMEM_PROJ = P_B0 + 4 * SZ_B;   // 75776 B  (stage 128*132*4=67584 fits)

__device__ __forceinline__ void proj_core(
    const __nv_bfloat16* __restrict__ Agh, const __nv_bfloat16* __restrict__ Agl,
    const __nv_bfloat16* __restrict__ Wgh, const __nv_bfloat16* __restrict__ Wgl,
    const float* __restrict__ bias,
    float* __restrict__ outf,
    __nv_bfloat16* __restrict__ outh, __nv_bfloat16* __restrict__ outl, int split)
{
    extern __shared__ char sm[];
    __nv_bfloat16* AT[2][2] = {
        {(__nv_bfloat16*)(sm + P_AH0), (__nv_bfloat16*)(sm + P_AH1)},
        {(__nv_bfloat16*)(sm + P_AL0), (__nv_bfloat16*)(sm + P_AL1)}};
    __nv_bfloat16* BT[2][2] = {
        {(__nv_bfloat16*)(sm + P_BH0), (__nv_bfloat16*)(sm + P_BH1)},
        {(__nv_bfloat16*)(sm + P_BL0), (__nv_bfloat16*)(sm + P_BL1)}};

    const int t  = threadIdx.x;
    const int w  = t >> 5;
    const int wm = w >> 2;
    const int wn = w & 3;
    const int m0 = blockIdx.y * 128;
    const int n0 = blockIdx.x * 128;

    FragC acc[4][2];
#pragma unroll
    for (int i = 0; i < 4; i++)
#pragma unroll
        for (int j = 0; j < 2; j++) wmma::fill_fragment(acc[i][j], 0.0f);

    const int ar = t >> 2, ac = (t & 3) * 8;
    const int br = t >> 4, bc = (t & 15) * 8;

#define LOAD_TILE(K0, BUF)                                                         \
    do {                                                                            \
        _Pragma("unroll")                                                           \
        for (int u = 0; u < 2; u++) {                                               \
            int r = ar + u * 64;                                                    \
            *(uint4*)&AT[0][BUF][r * ALD2 + ac] =                                   \
                *(const uint4*)&Agh[(size_t)(m0 + r) * Dc + (K0) + ac];             \
            *(uint4*)&AT[1][BUF][r * ALD2 + ac] =                                   \
                *(const uint4*)&Agl[(size_t)(m0 + r) * Dc + (K0) + ac];             \
            int rb = br + u * 16;                                                   \
            *(uint4*)&BT[0][BUF][rb * BLD2 + bc] =                                  \
                *(const uint4*)&Wgh[(size_t)((K0) + rb) * Dc + n0 + bc];            \
            *(uint4*)&BT[1][BUF][rb * BLD2 + bc] =                                  \
                *(const uint4*)&Wgl[(size_t)((K0) + rb) * Dc + n0 + bc];            \
        }                                                                           \
    } while (0)

    LOAD_TILE(0, 0);
    __syncthreads();

    for (int kt = 0; kt < 32; kt++) {
        int cur = kt & 1;
        if (kt < 31) LOAD_TILE((kt + 1) * 32, cur ^ 1);
#pragma unroll
        for (int ks = 0; ks < 32; ks += 16) {
            FragA ah[4], al[4];
#pragma unroll
            for (int i = 0; i < 4; i++) {
                wmma::load_matrix_sync(ah[i], &AT[0][cur][(wm * 64 + i * 16) * ALD2 + ks], ALD2);
                wmma::load_matrix_sync(al[i], &AT[1][cur][(wm * 64 + i * 16) * ALD2 + ks], ALD2);
            }
#pragma unroll
            for (int j = 0; j < 2; j++) {
                FragBR bh, bl;
                wmma::load_matrix_sync(bh, &BT[0][cur][ks * BLD2 + wn * 32 + j * 16], BLD2);
                wmma::load_matrix_sync(bl, &BT[1][cur][ks * BLD2 + wn * 32 + j * 16], BLD2);
#pragma unroll
                for (int i = 0; i < 4; i++) {
                    wmma::mma_sync(acc[i][j], ah[i], bh, acc[i][j]);
                    wmma::mma_sync(acc[i][j], ah[i], bl, acc[i][j]);
                    wmma::mma_sync(acc[i][j], al[i], bh, acc[i][j]);
                }
            }
        }
        __syncthreads();
    }
#undef LOAD_TILE

    // epilogue: stage fp32 tile in smem, then bias-add + (split ? bf16 hi/lo : fp32)
    float* Stage = (float*)sm;
#pragma unroll
    for (int i = 0; i < 4; i++)
#pragma unroll
        for (int j = 0; j < 2; j++)
            wmma::store_matrix_sync(&Stage[(wm * 64 + i * 16) * SLD + wn * 32 + j * 16],
                                    acc[i][j], SLD, wmma::mem_row_major);
    __syncthreads();

#pragma unroll
    for (int u = 0; u < 8; u++) {
        int idx = t + u * 256;
        int r = idx >> 4, c = (idx & 15) * 8;
        float4 b0 = *(const float4*)&bias[n0 + c];
        float4 b1 = *(const float4*)&bias[n0 + c + 4];
        const float* sp = &Stage[r * SLD + c];
        float fv[8];
        fv[0] = sp[0] + b0.x; fv[1] = sp[1] + b0.y; fv[2] = sp[2] + b0.z; fv[3] = sp[3] + b0.w;
        fv[4] = sp[4] + b1.x; fv[5] = sp[5] + b1.y; fv[6] = sp[6] + b1.z; fv[7] = sp[7] + b1.w;
        if (split) {
            __nv_bfloat16 hh[8], ll[8];
#pragma unroll
            for (int e = 0; e < 8; e++) split2(fv[e], hh[e], ll[e]);
            int m = m0 + r, n = n0 + c;
            size_t o = (((size_t)((m >> 11) * Hc + (n >> 6))) * Sc + (m & 2047)) * DEPTHc
                       + (n & 63);
            *(uint4*)&outh[o] = *(uint4*)hh;
            *(uint4*)&outl[o] = *(uint4*)ll;
        } else {
            size_t o = (size_t)(m0 + r) * Dc + n0 + c;
            *(float4*)&outf[o]     = make_float4(fv[0], fv[1], fv[2], fv[3]);
            *(float4*)&outf[o + 4] = make_float4(fv[4], fv[5], fv[6], fv[7]);
        }
    }
}

__global__ __launch_bounds__(256, 2) void proj_qkv(
    const __nv_bfloat16* __restrict__ inh, const __nv_bfloat16* __restrict__ inl,
    const __nv_bfloat16* __restrict__ wh,  const __nv_bfloat16* __restrict__ wl,
    const float* __restrict__ bQ, const float* __restrict__ bK, const float* __restrict__ bV,
    __nv_bfloat16* __restrict__ qh, __nv_bfloat16* __restrict__ ql,
    __nv_bfloat16* __restrict__ kh, __nv_bfloat16* __restrict__ kl,
    __nv_bfloat16* __restrict__ vh, __nv_bfloat16* __restrict__ vl)
{
    int z = blockIdx.z;
    const __nv_bfloat16* Agh = inh + (size_t)z * ACT_N;
    const __nv_bfloat16* Agl = inl + (size_t)z * ACT_N;
    const __nv_bfloat16* Wgh = wh + (size_t)z * W_N;
    const __nv_bfloat16* Wgl = wl + (size_t)z * W_N;
    const float* bias = (z == 0) ? bQ : (z == 1) ? bK : bV;
    __nv_bfloat16* oh = (z == 0) ? qh : (z == 1) ? kh : vh;
    __nv_bfloat16* ol = (z == 0) ? ql : (z == 1) ? kl : vl;
    proj_core(Agh, Agl, Wgh, Wgl, bias, nullptr, oh, ol, 1);
}

__global__ __launch_bounds__(256, 2) void proj_o(
    const __nv_bfloat16* __restrict__ ctxh, const __nv_bfloat16* __restrict__ ctxl,
    const __nv_bfloat16* __restrict__ wh,   const __nv_bfloat16* __restrict__ wl,
    const float* __restrict__ bias, float* __restrict__ out)
{
    proj_core(ctxh, ctxl, wh, wl, bias, out, nullptr, nullptr, 0);
}

// ---------------------------------------------------------------------------
// Fused attention (pre-split bf16 q/k/v), single pass, no-max softmax.
// ---------------------------------------------------------------------------
constexpr int QLD  = 72;
constexpr int PSLD = 68;

constexpr int SZ_BF = 64 * QLD * 2;
constexpr int OFF_QH = 0;
constexpr int OFF_QL = OFF_QH + SZ_BF;
constexpr int OFF_KH = OFF_QL + SZ_BF;
constexpr int OFF_KL = OFF_KH + SZ_BF;
constexpr int OFF_VH = OFF_KL + SZ_BF;
constexpr int OFF_VL = OFF_VH + SZ_BF;
constexpr int OFF_PH = OFF_VL + SZ_BF;
constexpr int OFF_PL = OFF_PH + SZ_BF;
constexpr int OFF_PS = OFF_PL + SZ_BF;
constexpr int OFF_RI = OFF_PS + 64 * PSLD * 4;
constexpr int SMEM_ATTN = OFF_RI + 64 * 4;   // ~91.6 KB -> 2 CTAs/SM

__global__ __launch_bounds__(256) void attn_fused(
    const __nv_bfloat16* __restrict__ qh_g, const __nv_bfloat16* __restrict__ ql_g,
    const __nv_bfloat16* __restrict__ kh_g, const __nv_bfloat16* __restrict__ kl_g,
    const __nv_bfloat16* __restrict__ vh_g, const __nv_bfloat16* __restrict__ vl_g,
    float* __restrict__ attn,
    __nv_bfloat16* __restrict__ ctxh, __nv_bfloat16* __restrict__ ctxl,
    float* __restrict__ invout)
{
    extern __shared__ char smraw[];
    __nv_bfloat16* Qh = (__nv_bfloat16*)(smraw + OFF_QH);
    __nv_bfloat16* Ql = (__nv_bfloat16*)(smraw + OFF_QL);
    __nv_bfloat16* Kh = (__nv_bfloat16*)(smraw + OFF_KH);
    __nv_bfloat16* Kl = (__nv_bfloat16*)(smraw + OFF_KL);
    __nv_bfloat16* Vh = (__nv_bfloat16*)(smraw + OFF_VH);
    __nv_bfloat16* Vl = (__nv_bfloat16*)(smraw + OFF_VL);
    __nv_bfloat16* Ph = (__nv_bfloat16*)(smraw + OFF_PH);
    __nv_bfloat16* Pl = (__nv_bfloat16*)(smraw + OFF_PL);
    float* Ps     = (float*)(smraw + OFF_PS);
    float* rowinv = (float*)(smraw + OFF_RI);

    const int t  = threadIdx.x;
    const int w  = t >> 5;
    const int wm = w >> 1;
    const int wn = w & 1;
    const int m0 = blockIdx.x * 64;
    const int bh = blockIdx.y;
    const int bb = bh >> 4, hh = bh & 15;

    const size_t hbase = (size_t)bh * Sc * DEPTHc;
    const int lr8 = t >> 3, lc8 = (t & 7) * 8;

    // load Q strip 64x64 (bf16 hi/lo, uint4)
#pragma unroll
    for (int u = 0; u < 2; u++) {
        int r = lr8 + u * 32;
        size_t g = hbase + (size_t)(m0 + r) * DEPTHc + lc8;
        *(uint4*)&Qh[r * QLD + lc8] = *(const uint4*)&qh_g[g];
        *(uint4*)&Ql[r * QLD + lc8] = *(const uint4*)&ql_g[g];
    }

    FragC accC[2];
#pragma unroll
    for (int j = 0; j < 2; j++) wmma::fill_fragment(accC[j], 0.0f);
    float rowsum = 0.0f;

    const int cr = t >> 2;
    const int cb = (t & 3) * 4;

    for (int kt = 0; kt < 32; kt++) {
        // load K, V tiles (bf16 hi/lo)
#pragma unroll
        for (int u = 0; u < 2; u++) {
            int r = lr8 + u * 32;
            size_t g = hbase + (size_t)(kt * 64 + r) * DEPTHc + lc8;
            *(uint4*)&Kh[r * QLD + lc8] = *(const uint4*)&kh_g[g];
            *(uint4*)&Kl[r * QLD + lc8] = *(const uint4*)&kl_g[g];
            *(uint4*)&Vh[r * QLD + lc8] = *(const uint4*)&vh_g[g];
            *(uint4*)&Vl[r * QLD + lc8] = *(const uint4*)&vl_g[g];
        }
        __syncthreads();

        // scores
        FragC s[2];
#pragma unroll
        for (int j = 0; j < 2; j++) wmma::fill_fragment(s[j], 0.0f);
#pragma unroll
        for (int d0 = 0; d0 < 64; d0 += 16) {
            FragA ah, al;
            wmma::load_matrix_sync(ah, &Qh[(wm * 16) * QLD + d0], QLD);
            wmma::load_matrix_sync(al, &Ql[(wm * 16) * QLD + d0], QLD);
#pragma unroll
            for (int j = 0; j < 2; j++) {
                FragBC bhf, blf;
                wmma::load_matrix_sync(bhf, &Kh[(wn * 32 + j * 16) * QLD + d0], QLD);
                wmma::load_matrix_sync(blf, &Kl[(wn * 32 + j * 16) * QLD + d0], QLD);
                wmma::mma_sync(s[j], ah, bhf, s[j]);
                wmma::mma_sync(s[j], ah, blf, s[j]);
                wmma::mma_sync(s[j], al, bhf, s[j]);
            }
        }
#pragma unroll
        for (int j = 0; j < 2; j++)
            wmma::store_matrix_sync(&Ps[(wm * 16) * PSLD + wn * 32 + j * 16],
                                    s[j], PSLD, wmma::mem_row_major);
        __syncthreads();

        // p = exp(scale*s): write unnormalized attn, split into Ph/Pl
        {
            float* adst = attn + ((size_t)bh * Sc + m0 + cr) * Sc + kt * 64;
            float lsum = 0.0f;
#pragma unroll
            for (int j = 0; j < 4; j++) {
                int c = cb + j * 16;
                float4 sv = *(const float4*)&Ps[cr * PSLD + c];
                float4 pv;
                pv.x = __expf(fminf(sv.x * SCALE, 80.0f));
                pv.y = __expf(fminf(sv.y * SCALE, 80.0f));
                pv.z = __expf(fminf(sv.z * SCALE, 80.0f));
                pv.w = __expf(fminf(sv.w * SCALE, 80.0f));
                lsum += pv.x + pv.y + pv.z + pv.w;
                *(float4*)(adst + c) = pv;
                int o = cr * QLD + c;
                split2(pv.x, Ph[o + 0], Pl[o + 0]); split2(pv.y, Ph[o + 1], Pl[o + 1]);
                split2(pv.z, Ph[o + 2], Pl[o + 2]); split2(pv.w, Ph[o + 3], Pl[o + 3]);
            }
            rowsum += lsum;
        }
        __syncthreads();

        // ctx += P @ V
#pragma unroll
        for (int ks = 0; ks < 64; ks += 16) {
            FragA ph, pl;
            wmma::load_matrix_sync(ph, &Ph[(wm * 16) * QLD + ks], QLD);
            wmma::load_matrix_sync(pl, &Pl[(wm * 16) * QLD + ks], QLD);
#pragma unroll
            for (int j = 0; j < 2; j++) {
                FragBR vh, vl;
                wmma::load_matrix_sync(vh, &Vh[ks * QLD + wn * 32 + j * 16], QLD);
                wmma::load_matrix_sync(vl, &Vl[ks * QLD + wn * 32 + j * 16], QLD);
                wmma::mma_sync(accC[j], ph, vh, accC[j]);
                wmma::mma_sync(accC[j], ph, vl, accC[j]);
                wmma::mma_sync(accC[j], pl, vh, accC[j]);
            }
        }
        __syncthreads();
    }

    // rowsum merge across the 4 threads owning each row
    {
        float rs = rowsum;
        rs += __shfl_xor_sync(0xffffffffu, rs, 1);
        rs += __shfl_xor_sync(0xffffffffu, rs, 2);
        float iv = 1.0f / rs;
        if ((t & 3) == 0) {
            rowinv[cr] = iv;
            invout[(size_t)bh * Sc + m0 + cr] = iv;
        }
    }
    __syncthreads();

    // write ctx normalized, split to bf16 hi/lo, merged-head layout
#pragma unroll
    for (int j = 0; j < 2; j++)
        wmma::store_matrix_sync(&Ps[(wm * 16) * PSLD + wn * 32 + j * 16],
                                accC[j], PSLD, wmma::mem_row_major);
    __syncthreads();
    {
        float iv = rowinv[cr];
        size_t base = ((size_t)(bb * Sc) + m0 + cr) * Dc + hh * DEPTHc;
#pragma unroll
        for (int j = 0; j < 4; j++) {
            int c = cb + j * 16;
            float4 vv = *(const float4*)&Ps[cr * PSLD + c];
            __nv_bfloat16 sh[4], sl[4];
            split2(vv.x * iv, sh[0], sl[0]); split2(vv.y * iv, sh[1], sl[1]);
            split2(vv.z * iv, sh[2], sl[2]); split2(vv.w * iv, sh[3], sl[3]);
            *(uint2*)&ctxh[base + c] = *(uint2*)sh;
            *(uint2*)&ctxl[base + c] = *(uint2*)sl;
        }
    }
}

// ---------------------------------------------------------------------------
__global__ __launch_bounds__(256) void rescale_attn(
    float* __restrict__ attn, const float* __restrict__ inv)
{
    size_t i = (size_t)blockIdx.x * blockDim.x + threadIdx.x;
    float iv = __ldg(&inv[i >> 9]);
    float4* p = (float4*)attn;
    float4 vv = p[i];
    vv.x *= iv; vv.y *= iv; vv.z *= iv; vv.w *= iv;
    p[i] = vv;
}

// ---------------------------------------------------------------------------
extern "C" void kernel_launch(void* const* d_in, const int* in_sizes, int n_in,
                              void* d_out, int out_size)
{
    const float* Q   = (const float*)d_in[0];
    const float* K   = (const float*)d_in[1];
    const float* V   = (const float*)d_in[2];
    const float* WQw = (const float*)d_in[3];
    const float* WQb = (const float*)d_in[4];
    const float* WKw = (const float*)d_in[5];
    const float* WKb = (const float*)d_in[6];
    const float* WVw = (const float*)d_in[7];
    const float* WVb = (const float*)d_in[8];
    const float* WOw = (const float*)d_in[9];
    const float* WOb = (const float*)d_in[10];
    float* out = (float*)d_out;

    __nv_bfloat16 *wh, *wl, *inh, *inl, *qh, *ql, *kh, *kl, *vh, *vl, *cth, *ctl;
    float *pfb, *pinv;
    cudaGetSymbolAddress((void**)&wh,  g_wh);
    cudaGetSymbolAddress((void**)&wl,  g_wl);
    cudaGetSymbolAddress((void**)&inh, g_inh);
    cudaGetSymbolAddress((void**)&inl, g_inl);
    cudaGetSymbolAddress((void**)&qh,  g_qh);
    cudaGetSymbolAddress((void**)&ql,  g_ql);
    cudaGetSymbolAddress((void**)&kh,  g_kh);
    cudaGetSymbolAddress((void**)&kl,  g_kl);
    cudaGetSymbolAddress((void**)&vh,  g_vh);
    cudaGetSymbolAddress((void**)&vl,  g_vl);
    cudaGetSymbolAddress((void**)&cth, g_ctxh);
    cudaGetSymbolAddress((void**)&ctl, g_ctxl);
    cudaGetSymbolAddress((void**)&pfb,  g_attn_fb);
    cudaGetSymbolAddress((void**)&pinv, g_inv);

    float* attn = ((long long)out_size >= OUT_ELEMS + ATTN_ELEMS)
                      ? out + OUT_ELEMS : pfb;

    static int smem_set = 0;
    if (!smem_set) {
        cudaFuncSetAttribute(attn_fused, cudaFuncAttributeMaxDynamicSharedMemorySize,
                             SMEM_ATTN);
        cudaFuncSetAttribute(proj_qkv, cudaFuncAttributeMaxDynamicSharedMemorySize,
                             SMEM_PROJ);
        cudaFuncSetAttribute(proj_o, cudaFuncAttributeMaxDynamicSharedMemorySize,
                             SMEM_PROJ);
        smem_set = 1;
    }

    dim3 blk(256);
    dim3 gSplW((unsigned)(W_N / 8 / 256), 4);       // 512 x 4
    dim3 gSplI((unsigned)(ACT_N / 8 / 256), 3);     // 4096 x 3
    dim3 gProjQKV(Dc / 128, M_TOT / 128, 3);        // 8 x 64 x 3
    dim3 gProjO(Dc / 128, M_TOT / 128);             // 8 x 64
    dim3 gAttn(Sc / 64, Bc * Hc);                   // 32 x 64
    dim3 gResc((unsigned)(ATTN_ELEMS / 4 / 256));

    presplit_w<<<gSplW, blk>>>(WQw, WKw, WVw, WOw, wh, wl);
    presplit_in<<<gSplI, blk>>>(Q, K, V, inh, inl);
    proj_qkv<<<gProjQKV, blk, SMEM_PROJ>>>(inh, inl, wh, wl, WQb, WKb, WVb,
                                           qh, ql, kh, kl, vh, vl);
    attn_fused<<<gAttn, blk, SMEM_ATTN>>>(qh, ql, kh, kl, vh, vl, attn, cth, ctl, pinv);
    rescale_attn<<<gResc, blk>>>(attn, pinv);
    proj_o<<<gProjO, blk, SMEM_PROJ>>>(cth, ctl, wh + 3 * W_N, wl + 3 * W_N, WOb, out);
}